// round 12
// baseline (speedup 1.0000x reference)
#include <cuda_runtime.h>
#include <cuda_bf16.h>

// ParametricInterpolation, round 10.
//
// PROTECTED NUMERICS (R6 pass, rel_err 7.7e-8 — rint-critical, do not alter):
//   p_k = rn( pb[k] * rn(1/scaler_k) )     (XLA divide-by-constant rewrite)
//   t2 = rn(t*t); t3 = rn(t2*t); t4 = rn(t2*t2)
//   cv = fmaf(p0,t4,0) -> fmaf(p1,t3,.) -> fmaf(p2,t2,.) -> fmaf(p3,t,.) -> +p4
//   ci = rintf(cv);  d = cv - ci (exact);  raw_pos = t - ci (exact int)
//
// Perf (R7 post-mortem): kernel is at/near the fixed launch-overhead floor
// (T_ovh ~5000cyc); smem staging + barrier bought nothing. This round trims
// the per-thread critical path instead:
//   - direct L2-resident gather LDGs (no smem, no __syncthreads)
//   - interior fast path: weight sums are compile-time constants when all
//     taps are in-bounds (m in [3,2044]) -> multiply by constant reciprocal
//     instead of two __fdiv_rn (<=2ulp, well inside 1e-3 tolerance)
//   - no zero-weight FMAs (s1: taps m-2..m+2, s2: taps m-3..m+1)

#ifndef SIG_LEN
#define SIG_LEN 2048
#endif

__global__ void ParametricInterpolation_kernel(
    const float* __restrict__ x,       // [B, N]
    const float* __restrict__ params,  // [B, 5]
    float* __restrict__ out,           // [B, N]
    float* __restrict__ curve,         // [B, N] or nullptr
    int B)
{
    const int N = SIG_LEN;
    int gid = blockIdx.x * blockDim.x + threadIdx.x;
    if (gid >= B * N) return;
    int b = gid >> 11;
    int i = gid & (N - 1);

    // ---- rint-critical pipeline (PROTECTED) ----
    const float r0 = __fdiv_rn(1.0f, 1e11f);   // constant-folded rn(1/c)
    const float r1 = __fdiv_rn(1.0f, 1e7f);
    const float r2 = __fdiv_rn(1.0f, 1e3f);

    const float* pb = params + b * 5;
    float p0 = __fmul_rn(__ldg(pb + 0), r0);
    float p1 = __fmul_rn(__ldg(pb + 1), r1);
    float p2 = __fmul_rn(__ldg(pb + 2), r2);
    float p3 = __ldg(pb + 3);
    float p4 = __ldg(pb + 4);

    float t  = (float)i;
    float t2 = __fmul_rn(t, t);
    float t3 = __fmul_rn(t2, t);
    float t4 = __fmul_rn(t2, t2);

    float cv = fmaf(p0, t4, 0.0f);
    cv = fmaf(p1, t3, cv);
    cv = fmaf(p2, t2, cv);
    cv = fmaf(p3, t,  cv);
    cv = __fadd_rn(cv, p4);

    float ci = rintf(cv);
    float d  = __fadd_rn(cv, -ci);

    float raw_pos = __fadd_rn(t, -ci);         // exact integer
    float np_f = fminf(fmaxf(raw_pos, 1.0f), 2047.0f);
    int m = (int)np_f;

    // ---- constant-weight gather ----
    const float W1 = 0.36787944117144233f;     // f32(exp(-1))
    const float W2 = 1.1253517471925912e-07f;  // f32(exp(-16))
    // Interior weight sum (ascending-j accumulation, constant-folded):
    const float WS = __fadd_rn(__fadd_rn(__fadd_rn(__fadd_rn(W2, W1), 1.0f), W1), W2);
    const float RW = __fdiv_rn(1.0f, WS);      // constant reciprocal

    const float* xr = x + b * N;
    float a1, a2;

    if (m >= 3 && m <= 2044) {
        // All 6 taps in-bounds: unconditional loads, constant weight sums.
        float xm3 = __ldg(xr + m - 3);
        float xm2 = __ldg(xr + m - 2);
        float xm1 = __ldg(xr + m - 1);
        float x0  = __ldg(xr + m);
        float xp1 = __ldg(xr + m + 1);
        float xp2 = __ldg(xr + m + 2);

        // s1: taps m-2..m+2, ascending j (same partial-sum order as before)
        float s1 = __fmul_rn(xm2, W2);
        s1 = fmaf(xm1, W1, s1);
        s1 = __fadd_rn(s1, x0);
        s1 = fmaf(xp1, W1, s1);
        s1 = fmaf(xp2, W2, s1);
        // s2: taps m-3..m+1 (center at m-1), ascending j
        float s2 = __fmul_rn(xm3, W2);
        s2 = fmaf(xm2, W1, s2);
        s2 = __fadd_rn(s2, xm1);
        s2 = fmaf(x0,  W1, s2);
        s2 = fmaf(xp1, W2, s2);

        a1 = __fmul_rn(s1, RW);
        a2 = __fmul_rn(s2, RW);
    } else {
        // Edge: bounds-checked, exact divides (rare).
        float s1 = 0.0f, w1s = 0.0f, s2 = 0.0f, w2s = 0.0f;
        #pragma unroll
        for (int o = -3; o <= 2; o++) {
            int j = m + o;
            if (j < 0 || j >= N) continue;
            float xv = __ldg(xr + j);
            float wk1 = (o == 0) ? 1.0f
                      : (o == -1 || o == 1) ? W1
                      : (o == -2 || o == 2) ? W2 : 0.0f;
            int o2 = o + 1;
            float wk2 = (o2 == 0) ? 1.0f
                      : (o2 == -1 || o2 == 1) ? W1
                      : (o2 == -2 || o2 == 2) ? W2 : 0.0f;
            s1  = fmaf(xv, wk1, s1);
            w1s = __fadd_rn(w1s, wk1);
            s2  = fmaf(xv, wk2, s2);
            w2s = __fadd_rn(w2s, wk2);
        }
        a1 = __fdiv_rn(s1, w1s);
        a2 = __fdiv_rn(s2, w2s);
    }

    // out = a1*(1-d) + a2*d
    float one_md = __fadd_rn(1.0f, -d);
    float o_val = __fadd_rn(__fmul_rn(a1, one_md), __fmul_rn(a2, d));

    out[gid] = o_val;
    if (curve) curve[gid] = cv;
}

extern "C" void kernel_launch(void* const* d_in, const int* in_sizes, int n_in,
                              void* d_out, int out_size)
{
    const float* x      = (const float*)d_in[0];   // [B, 2048] f32
    const float* params = (const float*)d_in[1];   // [B, 5]    f32
    float* out = (float*)d_out;

    int B = in_sizes[1] / 5;           // 16
    int total = B * SIG_LEN;           // 32768

    float* curve = (out_size >= 2 * total) ? (out + total) : nullptr;

    int threads = 256;
    int blocks = (total + threads - 1) / threads;  // 128
    ParametricInterpolation_kernel<<<blocks, threads>>>(x, params, out, curve, B);
}